// round 7
// baseline (speedup 1.0000x reference)
#include <cuda_runtime.h>

#define SDIM 7
#define NCELL 49
#define CH 30
#define NC 20
#define CONF_THR 0.25f
#define IOU_THR 0.45f
#define EPSF 1e-6f
#define NV4F 367   // full float4s in 1470 floats (tail of 2 floats)

__device__ __forceinline__ float fsig(float v) {
    return __fdividef(1.0f, 1.0f + __expf(-v));
}

__global__ void __launch_bounds__(32, 1)
yolo_decode_nms_kernel(const float4* __restrict__ x4,
                       const float* __restrict__ x,
                       float* __restrict__ out, int out_size) {
    __shared__ float4 xs4[NV4F + 1];
    __shared__ float conf[52];                    // padded for float4 reads
    __shared__ int   clsi[52];                    // padded for int4 reads
    __shared__ float4 geo4[NCELL];                // xmin,ymin,xmax,ymax (orig order)
    __shared__ float area[NCELL];
    __shared__ unsigned long long suppm[NCELL];   // keyed by rank; bits = orig idx
    __shared__ unsigned long long selfb[NCELL];   // keyed by rank; 1<<orig idx
    __shared__ unsigned long long nzmask;

    float* xs = (float*)xs4;
    const int t = threadIdx.x;   // 0..31, single warp

    // ---- Phase 0: coalesced staging (12 LDG.128/lane max) ----
    #pragma unroll
    for (int k = 0; k < 12; k++) {
        const int idx = t + 32 * k;
        if (idx < NV4F) xs4[idx] = x4[idx];
    }
    if (t < 2) xs[NV4F * 4 + t] = x[NV4F * 4 + t];
    if (t == 0) nzmask = 0ull;
    if (t < 3) { conf[NCELL + t] = -1e30f; clsi[NCELL + t] = -1; }
    __syncwarp();

    // ---- Phase 1: decode 2 cells per thread; boxes stay in registers ----
    float fcls[2], mcf[2], cxv[2], cyv[2], wv[2], hv[2];
    int mcls[2];
    #pragma unroll
    for (int c = 0; c < 2; c++) {
        fcls[c] = 0.f; mcf[c] = -1.f; cxv[c] = cyv[c] = wv[c] = hv[c] = 0.f; mcls[c] = -2 - c;
        const int cell = t + 32 * c;
        if (cell < NCELL) {
            const float2* cp = (const float2*)(xs + cell * CH);  // 8B-aligned
            float r[CH];
            #pragma unroll
            for (int k = 0; k < CH / 2; k++) {
                const float2 v = cp[k];
                r[2 * k] = v.x; r[2 * k + 1] = v.y;
            }
            float m01 = fmaxf(r[0], r[1]),   m23 = fmaxf(r[2], r[3]);
            float m45 = fmaxf(r[4], r[5]),   m67 = fmaxf(r[6], r[7]);
            float m89 = fmaxf(r[8], r[9]),   mab = fmaxf(r[10], r[11]);
            float mcd = fmaxf(r[12], r[13]), mef = fmaxf(r[14], r[15]);
            float mgh = fmaxf(r[16], r[17]), mij = fmaxf(r[18], r[19]);
            float q0 = fmaxf(m01, m23), q1 = fmaxf(m45, m67), q2 = fmaxf(m89, mab);
            float q3 = fmaxf(mcd, mef), q4 = fmaxf(mgh, mij);
            float mv = fmaxf(fmaxf(fmaxf(q0, q1), fmaxf(q2, q3)), q4);
            unsigned em = 0;
            #pragma unroll
            for (int i = 0; i < NC; i++) em |= (r[i] == mv) ? (1u << i) : 0u;
            const int cl = __ffs(em) - 1;       // first index wins ties
            mcls[c] = cl;
            fcls[c] = (float)cl;

            const float c0 = r[NC + 0], c1 = r[NC + 5];
            const int bb = (c1 > c0) ? 1 : 0;   // box0 wins ties
            const int boff = NC + 5 * bb;
            const float pc = fsig(fmaxf(c0, c1));
            const float bx = fsig(r[boff + 1]);
            const float by = fsig(r[boff + 2]);
            const float bw = fsig(r[boff + 3]);
            const float bh = fsig(r[boff + 4]);

            const int gy = cell / SDIM;
            const int gx = cell - gy * SDIM;
            const float stride = 448.0f / (float)SDIM;  // 64
            const float cx = (bx + (float)gx) * stride;
            const float cy = (by + (float)gy) * stride;
            const float w  = bw * (float)SDIM * stride;
            const float h  = bh * (float)SDIM * stride;
            mcf[c] = pc; cxv[c] = cx; cyv[c] = cy; wv[c] = w; hv[c] = h;

            conf[cell] = pc;
            clsi[cell] = cl;
            const float xmin = cx - 0.5f * w, xmax = cx + 0.5f * w;
            const float ymin = cy - 0.5f * h, ymax = cy + 0.5f * h;
            geo4[cell] = make_float4(xmin, ymin, xmax, ymax);
            area[cell] = fabsf((xmax - xmin) * (ymax - ymin));
        }
    }
    // keep0 from two register ballots (cells 0..31, 32..48)
    const unsigned b0 = __ballot_sync(0xffffffffu, mcf[0] > CONF_THR);
    const unsigned b1 = __ballot_sync(0xffffffffu, (t + 32 < NCELL) && (mcf[1] > CONF_THR));
    unsigned long long keepm = (unsigned long long)b0 | ((unsigned long long)b1 << 32);
    __syncwarp();

    // ---- Phase 2: rank + same-class lower-priority prefilter + sparse IoU ----
    int rankv[2];
    #pragma unroll
    for (int c = 0; c < 2; c++) {
        rankv[c] = 0;
        const int cell = t + 32 * c;
        if (cell < NCELL) {
            const float mc = mcf[c];
            const int   ml = mcls[c];
            int rank = 0;
            unsigned long long cm = 0ull;
            const float4* cp4 = (const float4*)conf;
            const int4*   ci4 = (const int4*)clsi;
            #pragma unroll
            for (int q = 0; q < 13; q++) {
                const float4 cf = cp4[q];
                const int4   cw = ci4[q];
                const int j0 = 4 * q;
                const bool h0 = (cf.x > mc) || (cf.x == mc && (j0 + 0) < cell);
                const bool h1 = (cf.y > mc) || (cf.y == mc && (j0 + 1) < cell);
                const bool h2 = (cf.z > mc) || (cf.z == mc && (j0 + 2) < cell);
                const bool h3 = (cf.w > mc) || (cf.w == mc && (j0 + 3) < cell);
                rank += (int)h0 + (int)h1 + (int)h2 + (int)h3;
                cm |= (unsigned long long)((cw.x == ml) & !h0 & ((j0 + 0) != cell)) << (j0 + 0);
                cm |= (unsigned long long)((cw.y == ml) & !h1 & ((j0 + 1) != cell)) << (j0 + 1);
                cm |= (unsigned long long)((cw.z == ml) & !h2 & ((j0 + 2) != cell)) << (j0 + 2);
                cm |= (unsigned long long)((cw.w == ml) & !h3 & ((j0 + 3) != cell)) << (j0 + 3);
            }
            rankv[c] = rank;
            const float4 g = geo4[cell];
            const float a_i = area[cell];
            unsigned long long m = 0ull;
            while (cm) {
                const int j = __ffsll((long long)cm) - 1;
                cm &= cm - 1ull;
                const float4 gj = geo4[j];
                const float iw = fmaxf(fminf(g.z, gj.z) - fmaxf(g.x, gj.x), 0.0f);
                const float ih = fmaxf(fminf(g.w, gj.w) - fmaxf(g.y, gj.y), 0.0f);
                const float inter = iw * ih;
                if (inter >= IOU_THR * (a_i + area[j] - inter + EPSF)) m |= (1ull << j);
            }
            if (m) {
                suppm[rank] = m;
                selfb[rank] = 1ull << cell;
                atomicOr(&nzmask, 1ull << rank);   // rare
            }
        }
    }
    __syncwarp();

    // ---- Phase 3: sparse sequential propagation (ascending rank) ----
    unsigned long long nz = nzmask;
    while (nz) {
        const int rr = __ffsll((long long)nz) - 1;
        nz &= nz - 1ull;
        if (keepm & selfb[rr]) keepm &= ~suppm[rr];
    }

    // ---- Output: register-direct, rank-addressed ----
    #pragma unroll
    for (int c = 0; c < 2; c++) {
        const int cell = t + 32 * c;
        if (cell < NCELL) {
            const float k = (float)((keepm >> cell) & 1ull);
            float2* o2 = (float2*)(out + rankv[c] * 6);   // 8B-aligned
            o2[0] = make_float2(fcls[c] * k, mcf[c] * k);
            o2[1] = make_float2(cxv[c] * k, cyv[c] * k);
            o2[2] = make_float2(wv[c] * k, hv[c] * k);
            const int koff = NCELL * 6 + rankv[c];
            if (koff < out_size) out[koff] = k;
        }
    }
}

extern "C" void kernel_launch(void* const* d_in, const int* in_sizes, int n_in,
                              void* d_out, int out_size) {
    const float* x = (const float*)d_in[0];
    float* out = (float*)d_out;
    yolo_decode_nms_kernel<<<1, 32>>>((const float4*)x, x, out, out_size);
}

// round 9
// speedup vs baseline: 1.2455x; 1.2455x over previous
#include <cuda_runtime.h>

#define SDIM 7
#define NCELL 49
#define CH 30
#define NC 20
#define CONF_THR 0.25f
#define IOU_THR 0.45f
#define EPSF 1e-6f
#define NFLOAT (NCELL * CH)   // 1470
#define NVEC4 (NFLOAT / 4)    // 367 (tail of 2)

__device__ __forceinline__ float fsig(float v) {
    return __fdividef(1.0f, 1.0f + __expf(-v));
}

__global__ void __launch_bounds__(64, 1)
yolo_decode_nms_kernel(const float4* __restrict__ x4,
                       const float* __restrict__ x,
                       float* __restrict__ out, int out_size) {
    __shared__ float4 xs4[NVEC4 + 1];
    __shared__ float conf[NCELL];
    __shared__ __align__(16) float srt[NCELL][6]; // sorted rows; 16B base -> each 24B row 8B-aligned
    __shared__ float4 geo4[NCELL];                // xmin, ymin, xmax, ymax (sorted)
    __shared__ float area[NCELL];
    __shared__ int clsi[52];                      // padded to int4 multiple
    __shared__ unsigned long long suppm[NCELL];
    __shared__ unsigned int bal[4];               // keep_lo, keep_hi, nz_lo, nz_hi

    float* xs = (float*)xs4;
    const int t = threadIdx.x;

    // ---- Phase 0: coalesced cooperative staging ----
    #pragma unroll
    for (int i = t; i < NVEC4; i += 64) xs4[i] = x4[i];
    if (t < 2) xs[NVEC4 * 4 + t] = x[NVEC4 * 4 + t];
    if (t < 3) clsi[NCELL + t] = -1;
    __syncthreads();

    // ---- Phase 1: decode (float2 loads, tree argmax on raw logits) ----
    float bx = 0.f, by = 0.f, bw = 0.f, bh = 0.f, myconf = 0.f;
    int myclsi = 0;
    if (t < NCELL) {
        const float2* c = (const float2*)(xs + t * CH);  // t*120B from 16B base, 8B-aligned
        float r[CH];
        #pragma unroll
        for (int k = 0; k < CH / 2; k++) {
            const float2 v = c[k];
            r[2 * k] = v.x; r[2 * k + 1] = v.y;
        }

        float m01 = fmaxf(r[0], r[1]),   m23 = fmaxf(r[2], r[3]);
        float m45 = fmaxf(r[4], r[5]),   m67 = fmaxf(r[6], r[7]);
        float m89 = fmaxf(r[8], r[9]),   mab = fmaxf(r[10], r[11]);
        float mcd = fmaxf(r[12], r[13]), mef = fmaxf(r[14], r[15]);
        float mgh = fmaxf(r[16], r[17]), mij = fmaxf(r[18], r[19]);
        float q0 = fmaxf(m01, m23), q1 = fmaxf(m45, m67), q2 = fmaxf(m89, mab);
        float q3 = fmaxf(mcd, mef), q4 = fmaxf(mgh, mij);
        float mv = fmaxf(fmaxf(fmaxf(q0, q1), fmaxf(q2, q3)), q4);
        unsigned em = 0;
        #pragma unroll
        for (int i = 0; i < NC; i++) em |= (r[i] == mv) ? (1u << i) : 0u;
        myclsi = __ffs(em) - 1;       // first index wins ties

        const float c0 = r[NC + 0], c1 = r[NC + 5];
        const int bb = (c1 > c0) ? 1 : 0;
        const int boff = NC + 5 * bb;
        myconf = fsig(fmaxf(c0, c1));
        bx = fsig(r[boff + 1]);
        by = fsig(r[boff + 2]);
        bw = fsig(r[boff + 3]);
        bh = fsig(r[boff + 4]);
        conf[t] = myconf;
    }
    __syncthreads();

    // ---- Phase 2: stable rank (conf desc) + scatter to sorted slots ----
    if (t < NCELL) {
        int rank = 0;
        #pragma unroll
        for (int j = 0; j < NCELL; j++) {
            const float cj = conf[j];
            if (cj > myconf || (cj == myconf && j < t)) rank++;
        }
        const int gy = t / SDIM;
        const int gx = t - gy * SDIM;
        const float stride = 448.0f / (float)SDIM;  // 64
        const float cx = (bx + (float)gx) * stride;
        const float cy = (by + (float)gy) * stride;
        const float w  = bw * (float)SDIM * stride;
        const float h  = bh * (float)SDIM * stride;
        srt[rank][0] = (float)myclsi;  srt[rank][1] = myconf;
        srt[rank][2] = cx;             srt[rank][3] = cy;
        srt[rank][4] = w;              srt[rank][5] = h;
        const float xmin = cx - 0.5f * w, xmax = cx + 0.5f * w;
        const float ymin = cy - 0.5f * h, ymax = cy + 0.5f * h;
        geo4[rank] = make_float4(xmin, ymin, xmax, ymax);
        area[rank] = fabsf((xmax - xmin) * (ymax - ymin));
        clsi[rank] = myclsi;
    }
    __syncthreads();

    // ---- Phase 3: my sorted row -> regs; sparse suppression masks ----
    float rcls = 0.f, rconf = 0.f, rcx = 0.f, rcy = 0.f, rw = 0.f, rh = 0.f;
    unsigned long long m = 0ull;
    if (t < NCELL) {
        const float2* row = (const float2*)(&srt[0][0] + t * 6);  // t*24B from 16B base
        const float2 p0 = row[0], p1 = row[1], p2 = row[2];
        rcls = p0.x; rconf = p0.y; rcx = p1.x; rcy = p1.y; rw = p2.x; rh = p2.y;

        const int ci = clsi[t];
        unsigned long long cm = 0ull;
        const int4* cp = (const int4*)clsi;
        #pragma unroll
        for (int q = 0; q < 13; q++) {
            const int4 w4 = cp[q];
            cm |= (unsigned long long)(w4.x == ci) << (4 * q + 0);
            cm |= (unsigned long long)(w4.y == ci) << (4 * q + 1);
            cm |= (unsigned long long)(w4.z == ci) << (4 * q + 2);
            cm |= (unsigned long long)(w4.w == ci) << (4 * q + 3);
        }
        cm &= ~((2ull << t) - 1ull);   // j > t only
        const float4 g = geo4[t];
        const float a_i = area[t];
        while (cm) {
            const int j = __ffsll((long long)cm) - 1;
            cm &= cm - 1ull;
            const float4 gj = geo4[j];
            const float iw = fmaxf(fminf(g.z, gj.z) - fmaxf(g.x, gj.x), 0.0f);
            const float ih = fmaxf(fminf(g.w, gj.w) - fmaxf(g.y, gj.y), 0.0f);
            const float inter = iw * ih;
            if (inter >= IOU_THR * (a_i + area[j] - inter + EPSF)) m |= (1ull << j);
        }
        suppm[t] = m;
    }
    const unsigned keepbal = __ballot_sync(0xffffffffu, (t < NCELL) && (rconf > CONF_THR));
    const unsigned nzbal = __ballot_sync(0xffffffffu, (t < NCELL) && (m != 0ull));
    if ((t & 31) == 0) { bal[t >> 5] = keepbal; bal[2 + (t >> 5)] = nzbal; }
    __syncthreads();

    // ---- Phase 4: sparse sequential keep propagation (rank order) ----
    unsigned long long keepm = (unsigned long long)bal[0] |
                               ((unsigned long long)bal[1] << 32);
    unsigned long long nz = (unsigned long long)bal[2] |
                            ((unsigned long long)bal[3] << 32);
    while (nz) {                         // ascending rank via ffs
        const int i = __ffsll((long long)nz) - 1;
        nz &= nz - 1ull;
        if ((keepm >> i) & 1ull) keepm &= ~suppm[i];
    }

    // ---- Output: register-direct; thread t owns rank t ----
    if (t < NCELL) {
        const float k = (float)((keepm >> t) & 1ull);
        float2* o2 = (float2*)(out + t * 6);   // out is cudaMalloc'd (256B-aligned); t*24B -> 8B-aligned
        o2[0] = make_float2(rcls * k, rconf * k);
        o2[1] = make_float2(rcx * k, rcy * k);
        o2[2] = make_float2(rw * k, rh * k);
        const int koff = NCELL * 6 + t;
        if (koff < out_size) out[koff] = k;
    }
}

extern "C" void kernel_launch(void* const* d_in, const int* in_sizes, int n_in,
                              void* d_out, int out_size) {
    const float* x = (const float*)d_in[0];
    float* out = (float*)d_out;
    yolo_decode_nms_kernel<<<1, 64>>>((const float4*)x, x, out, out_size);
}

// round 10
// speedup vs baseline: 1.2977x; 1.0419x over previous
#include <cuda_runtime.h>

#define SDIM 7
#define NCELL 49
#define CH 30
#define NC 20
#define CONF_THR 0.25f
#define IOU_THR 0.45f
#define EPSF 1e-6f
#define NFLOAT (NCELL * CH)   // 1470
#define NVEC4 (NFLOAT / 4)    // 367 (tail of 2)

__device__ __forceinline__ float fsig(float v) {
    return __fdividef(1.0f, 1.0f + __expf(-v));
}

__global__ void __launch_bounds__(64, 1)
yolo_decode_nms_kernel(const float4* __restrict__ x4,
                       const float* __restrict__ x,
                       float* __restrict__ out, int out_size) {
    __shared__ float4 xs4[NVEC4 + 1];
    __shared__ __align__(16) float conf[52];      // padded for float4 reads
    __shared__ __align__(16) float srt[NCELL][6]; // sorted rows; 24B rows from 16B base -> 8B-aligned
    __shared__ float4 geo4[NCELL];                // xmin, ymin, xmax, ymax (sorted)
    __shared__ float area[NCELL];
    __shared__ int clsi[52];                      // padded to int4 multiple
    __shared__ unsigned long long suppm[NCELL];
    __shared__ unsigned int bal[4];               // kc_lo, kc_hi (phase1), nz_lo, nz_hi

    float* xs = (float*)xs4;
    const int t = threadIdx.x;

    // ---- Phase 0: coalesced cooperative staging + pad init ----
    #pragma unroll
    for (int i = t; i < NVEC4; i += 64) xs4[i] = x4[i];
    if (t < 2) xs[NVEC4 * 4 + t] = x[NVEC4 * 4 + t];
    if (t < 3) { clsi[NCELL + t] = -1; conf[NCELL + t] = -1e30f; }
    __syncthreads();

    // ---- Phase 1: decode (float2 loads, tree argmax on raw logits) ----
    float bx = 0.f, by = 0.f, bw = 0.f, bh = 0.f, myconf = -1e30f;
    int myclsi = 0;
    if (t < NCELL) {
        const float2* c = (const float2*)(xs + t * CH);  // t*120B from 16B base, 8B-aligned
        float r[CH];
        #pragma unroll
        for (int k = 0; k < CH / 2; k++) {
            const float2 v = c[k];
            r[2 * k] = v.x; r[2 * k + 1] = v.y;
        }

        float m01 = fmaxf(r[0], r[1]),   m23 = fmaxf(r[2], r[3]);
        float m45 = fmaxf(r[4], r[5]),   m67 = fmaxf(r[6], r[7]);
        float m89 = fmaxf(r[8], r[9]),   mab = fmaxf(r[10], r[11]);
        float mcd = fmaxf(r[12], r[13]), mef = fmaxf(r[14], r[15]);
        float mgh = fmaxf(r[16], r[17]), mij = fmaxf(r[18], r[19]);
        float q0 = fmaxf(m01, m23), q1 = fmaxf(m45, m67), q2 = fmaxf(m89, mab);
        float q3 = fmaxf(mcd, mef), q4 = fmaxf(mgh, mij);
        float mv = fmaxf(fmaxf(fmaxf(q0, q1), fmaxf(q2, q3)), q4);
        unsigned em = 0;
        #pragma unroll
        for (int i = 0; i < NC; i++) em |= (r[i] == mv) ? (1u << i) : 0u;
        myclsi = __ffs(em) - 1;       // first index wins ties

        const float c0 = r[NC + 0], c1 = r[NC + 5];
        const int bb = (c1 > c0) ? 1 : 0;
        const int boff = NC + 5 * bb;
        myconf = fsig(fmaxf(c0, c1));
        bx = fsig(r[boff + 1]);
        by = fsig(r[boff + 2]);
        bw = fsig(r[boff + 3]);
        bh = fsig(r[boff + 4]);
        conf[t] = myconf;
    }
    // K = #{conf > THR} is order-invariant: ballot here, in original index order
    const unsigned kcbal = __ballot_sync(0xffffffffu, (t < NCELL) && (myconf > CONF_THR));
    if ((t & 31) == 0) bal[t >> 5] = kcbal;
    __syncthreads();

    // ---- Phase 2: stable rank (conf desc, float4 reads) + scatter to sorted slots ----
    if (t < NCELL) {
        int rank = 0;
        const float4* cp4 = (const float4*)conf;
        #pragma unroll
        for (int q = 0; q < 13; q++) {
            const float4 cf = cp4[q];
            const int j0 = 4 * q;
            rank += (cf.x > myconf || (cf.x == myconf && (j0 + 0) < t));
            rank += (cf.y > myconf || (cf.y == myconf && (j0 + 1) < t));
            rank += (cf.z > myconf || (cf.z == myconf && (j0 + 2) < t));
            rank += (cf.w > myconf || (cf.w == myconf && (j0 + 3) < t));
        }
        const int gy = t / SDIM;
        const int gx = t - gy * SDIM;
        const float stride = 448.0f / (float)SDIM;  // 64
        const float cx = (bx + (float)gx) * stride;
        const float cy = (by + (float)gy) * stride;
        const float w  = bw * (float)SDIM * stride;
        const float h  = bh * (float)SDIM * stride;
        srt[rank][0] = (float)myclsi;  srt[rank][1] = myconf;
        srt[rank][2] = cx;             srt[rank][3] = cy;
        srt[rank][4] = w;              srt[rank][5] = h;
        const float xmin = cx - 0.5f * w, xmax = cx + 0.5f * w;
        const float ymin = cy - 0.5f * h, ymax = cy + 0.5f * h;
        geo4[rank] = make_float4(xmin, ymin, xmax, ymax);
        area[rank] = fabsf((xmax - xmin) * (ymax - ymin));
        clsi[rank] = myclsi;
    }
    __syncthreads();

    // ---- Phase 3: my sorted row -> regs; sparse suppression masks (thread t = rank t) ----
    float rcls = 0.f, rconf = 0.f, rcx = 0.f, rcy = 0.f, rw = 0.f, rh = 0.f;
    unsigned long long m = 0ull;
    if (t < NCELL) {
        const float2* row = (const float2*)(&srt[0][0] + t * 6);  // t*24B from 16B base
        const float2 p0 = row[0], p1 = row[1], p2 = row[2];
        rcls = p0.x; rconf = p0.y; rcx = p1.x; rcy = p1.y; rw = p2.x; rh = p2.y;

        const int ci = clsi[t];
        unsigned long long cm = 0ull;
        const int4* cp = (const int4*)clsi;
        #pragma unroll
        for (int q = 0; q < 13; q++) {
            const int4 w4 = cp[q];
            cm |= (unsigned long long)(w4.x == ci) << (4 * q + 0);
            cm |= (unsigned long long)(w4.y == ci) << (4 * q + 1);
            cm |= (unsigned long long)(w4.z == ci) << (4 * q + 2);
            cm |= (unsigned long long)(w4.w == ci) << (4 * q + 3);
        }
        cm &= ~((2ull << t) - 1ull);   // j > t only
        const float4 g = geo4[t];
        const float a_i = area[t];
        while (cm) {
            const int j = __ffsll((long long)cm) - 1;
            cm &= cm - 1ull;
            const float4 gj = geo4[j];
            const float iw = fmaxf(fminf(g.z, gj.z) - fmaxf(g.x, gj.x), 0.0f);
            const float ih = fmaxf(fminf(g.w, gj.w) - fmaxf(g.y, gj.y), 0.0f);
            const float inter = iw * ih;
            if (inter >= IOU_THR * (a_i + area[j] - inter + EPSF)) m |= (1ull << j);
        }
        suppm[t] = m;
    }
    const unsigned nzbal = __ballot_sync(0xffffffffu, (t < NCELL) && (m != 0ull));
    if ((t & 31) == 0) bal[2 + (t >> 5)] = nzbal;
    __syncthreads();

    // ---- Phase 4: keep0 = rank-prefix of length K; sparse propagation (rank order) ----
    const int K = __popc(bal[0]) + __popc(bal[1]);   // sorted desc => keep0 = ranks [0,K)
    unsigned long long keepm = (1ull << K) - 1ull;   // K <= 49 < 64
    unsigned long long nz = (unsigned long long)bal[2] |
                            ((unsigned long long)bal[3] << 32);
    while (nz) {                         // ascending rank via ffs
        const int i = __ffsll((long long)nz) - 1;
        nz &= nz - 1ull;
        if ((keepm >> i) & 1ull) keepm &= ~suppm[i];
    }

    // ---- Output: register-direct; thread t owns rank t ----
    if (t < NCELL) {
        const float k = (float)((keepm >> t) & 1ull);
        float2* o2 = (float2*)(out + t * 6);   // out 256B-aligned; t*24B -> 8B-aligned
        o2[0] = make_float2(rcls * k, rconf * k);
        o2[1] = make_float2(rcx * k, rcy * k);
        o2[2] = make_float2(rw * k, rh * k);
        out[NCELL * 6 + t] = k;
    }
}

extern "C" void kernel_launch(void* const* d_in, const int* in_sizes, int n_in,
                              void* d_out, int out_size) {
    const float* x = (const float*)d_in[0];
    float* out = (float*)d_out;
    yolo_decode_nms_kernel<<<1, 64>>>((const float4*)x, x, out, out_size);
}